// round 16
// baseline (speedup 1.0000x reference)
#include <cuda_runtime.h>
#include <cuda_fp16.h>
#include <math.h>
#include <stdint.h>

#define D_MODEL 768
#define NUM_HEADS 12
#define DKH 64
#define BATCH 2
#define SEQ 4096
#define MROWS (BATCH * SEQ)   // 8192
#define NBH (BATCH * NUM_HEADS)

#define QSCALE 0.18033688011112042f      // log2(e)/8
#define SHIFT_LOG2 5.770780163555855f    // 4 nats in log2

// ---------------- scratch (device globals; no allocation) ----------------
#define QKV_ELEMS ((size_t)NBH * SEQ * DKH)
#define XN ((size_t)MROWS * D_MODEL)
#define WN ((size_t)D_MODEL * D_MODEL)
__device__ __half g_qh[QKV_ELEMS];       // [bh][s][d], prescaled log2e/8, hi only
__device__ __half g_kh[QKV_ELEMS];       // hi only
__device__ __half g_vth[QKV_ELEMS];      // [bh][d][s], hi only
__device__ __half g_xqh[XN], g_xql[XN];
__device__ __half g_xkh[XN], g_xkl[XN];
__device__ __half g_xvh[XN], g_xvl[XN];
__device__ __half g_wqh[WN];
__device__ __half g_wkh[WN];
__device__ __half g_wvh[WN];
__device__ __half g_woh[WN], g_wol[WN];
__device__ __half g_ath[XN];             // attention out, hi only
__device__ int    g_maxk2[NBH];          // max ||k||^2 as float bits (atomicMax)

// ---------------- helpers ----------------
__device__ __forceinline__ uint32_t smem_u32(const void* p) {
    return (uint32_t)__cvta_generic_to_shared(p);
}
__device__ __forceinline__ uint32_t pk(__half2 h) {
    union { __half2 h; uint32_t u; } x; x.h = h; return x.u;
}
__device__ __forceinline__ void ldsm_x4(uint32_t a, uint32_t& r0, uint32_t& r1,
                                        uint32_t& r2, uint32_t& r3) {
    asm volatile("ldmatrix.sync.aligned.m8n8.x4.shared.b16 {%0,%1,%2,%3}, [%4];"
                 : "=r"(r0), "=r"(r1), "=r"(r2), "=r"(r3) : "r"(a));
}
__device__ __forceinline__ void mma4(float* c, const uint32_t* a, uint32_t b0, uint32_t b1) {
    asm volatile(
        "mma.sync.aligned.m16n8k16.row.col.f32.f16.f16.f32 "
        "{%0,%1,%2,%3}, {%4,%5,%6,%7}, {%8,%9}, {%0,%1,%2,%3};"
        : "+f"(c[0]), "+f"(c[1]), "+f"(c[2]), "+f"(c[3])
        : "r"(a[0]), "r"(a[1]), "r"(a[2]), "r"(a[3]), "r"(b0), "r"(b1));
}
__device__ __forceinline__ void split2(float x, float y, uint32_t& hi, uint32_t& lo) {
    __half2 h = __floats2half2_rn(x, y);
    float rx = x - __half2float(__low2half(h));
    float ry = y - __half2float(__high2half(h));
    hi = pk(h);
    lo = pk(__floats2half2_rn(rx, ry));
}
__device__ __forceinline__ void cpa16(uint32_t s, const void* g) {
    asm volatile("cp.async.cg.shared.global [%0], [%1], 16;" :: "r"(s), "l"(g));
}
__device__ __forceinline__ void cpa_commit() {
    asm volatile("cp.async.commit_group;");
}
__device__ __forceinline__ float ex2(float x) {
    float y;
    asm("ex2.approx.f32 %0, %1;" : "=f"(y) : "f"(x));
    return y;
}
__device__ __forceinline__ float h2sq(uint32_t u) {
    float2 f = __half22float2(*(__half2*)&u);
    return f.x * f.x + f.y * f.y;
}

// =========================================================================
// Fused converter: y = 0..2 activations hi+lo; 3..5 weights hi; 6 Wo hi+lo.
// =========================================================================
__global__ __launch_bounds__(256) void cvt_all(
    const float* __restrict__ q, const float* __restrict__ k,
    const float* __restrict__ v, const float* __restrict__ wq,
    const float* __restrict__ wk, const float* __restrict__ wv,
    const float* __restrict__ wo)
{
    const int y = blockIdx.y;
    const float* src;
    __half *hi, *lo;
    int n4;
    switch (y) {
        case 0: src = q;  hi = g_xqh; lo = g_xql;   n4 = XN / 4; break;
        case 1: src = k;  hi = g_xkh; lo = g_xkl;   n4 = XN / 4; break;
        case 2: src = v;  hi = g_xvh; lo = g_xvl;   n4 = XN / 4; break;
        case 3: src = wq; hi = g_wqh; lo = nullptr; n4 = WN / 4; break;
        case 4: src = wk; hi = g_wkh; lo = nullptr; n4 = WN / 4; break;
        case 5: src = wv; hi = g_wvh; lo = nullptr; n4 = WN / 4; break;
        default: src = wo; hi = g_woh; lo = g_wol;  n4 = WN / 4; break;
    }
    uint32_t* hio = (uint32_t*)hi;
    uint32_t* loo = (uint32_t*)lo;
    for (int i = blockIdx.x * 256 + threadIdx.x; i < n4; i += gridDim.x * 256) {
        float4 f = ((const float4*)src)[i];
        uint32_t h0, l0, h1, l1;
        split2(f.x, f.y, h0, l0);
        split2(f.z, f.w, h1, l1);
        hio[2 * i] = h0; hio[2 * i + 1] = h1;
        if (lo) { loo[2 * i] = l0; loo[2 * i + 1] = l1; }
    }
}

// =========================================================================
// kmax: grid (NBH, 8), atomicMax on float bits of ||k||^2 (all >= 0).
// =========================================================================
__global__ __launch_bounds__(256) void kmax_kernel(const __half* __restrict__ kh,
                                                   int* __restrict__ maxk2)
{
    __shared__ float red[256];
    const int bh = blockIdx.x;
    const int part = blockIdx.y;
    const int rows = SEQ / 8;
    const __half* base = kh + (size_t)bh * SEQ * DKH + (size_t)part * rows * DKH;
    float mx = 0.f;
    for (int r = threadIdx.x; r < rows; r += 256) {
        const uint4* p = (const uint4*)(base + (size_t)r * DKH);
        float s = 0.f;
        #pragma unroll
        for (int i = 0; i < 8; i++) {
            uint4 u = p[i];
            s += h2sq(u.x) + h2sq(u.y) + h2sq(u.z) + h2sq(u.w);
        }
        mx = fmaxf(mx, s);
    }
    red[threadIdx.x] = mx;
    __syncthreads();
    for (int st = 128; st > 0; st >>= 1) {
        if (threadIdx.x < st) red[threadIdx.x] = fmaxf(red[threadIdx.x], red[threadIdx.x + st]);
        __syncthreads();
    }
    if (threadIdx.x == 0) atomicMax(&maxk2[bh], __float_as_int(red[0]));
}

// =========================================================================
// GEMM body, tile 128x128, K-chunk 32, cp.async THREE-stage pipeline. 2-pass.
// SMEM slots per stage: [0]=A hi, [1]=A lo OR W lo, [2]=W hi.
// =========================================================================
#define GBM 128
#define GBN 128
#define GKC 32
#define GSTR 40
#define NKC (D_MODEL / GKC)      // 24
#define GS_T (128 * GSTR)
#define GS_STAGE (3 * GS_T)
#define GEM_SMEM (3 * GS_STAGE * 2)  // 92160 bytes

__device__ __forceinline__ void gemm_body(
    __half* gs, int row0, int col0,
    const __half* __restrict__ Ah, const __half* __restrict__ Al,
    const __half* __restrict__ Wh, const __half* __restrict__ Wl,
    const float* __restrict__ bias, float* __restrict__ outf,
    __half* __restrict__ outh, int mode)
{
    const int tid = threadIdx.x;
    const int w = tid >> 5;
    const int lane = tid & 31;
    const int blk = lane >> 3;
    const int lrow = lane & 7;
    const bool useAlo = (Al != nullptr);
    const bool useBlo = (Wl != nullptr);

    float acc[16][4] = {};

    auto issue = [&](int kc, int st) {
        const int k0 = kc * GKC;
        __half* S = gs + st * GS_STAGE;
        #pragma unroll
        for (int i = 0; i < 6; i++) {
            const int ci = tid + i * 256;
            const int slot = ci >> 9;
            const int idx = ci & 511;
            const int r = idx >> 2, c4 = idx & 3;
            const __half* src;
            if (slot == 0) {
                src = Ah + (size_t)(row0 + r) * D_MODEL + k0 + c4 * 8;
            } else if (slot == 1) {
                if (useAlo)      src = Al + (size_t)(row0 + r) * D_MODEL + k0 + c4 * 8;
                else if (useBlo) src = Wl + (size_t)(col0 + r) * D_MODEL + k0 + c4 * 8;
                else continue;
            } else {
                src = Wh + (size_t)(col0 + r) * D_MODEL + k0 + c4 * 8;
            }
            cpa16(smem_u32(S + slot * GS_T + r * GSTR + c4 * 8), src);
        }
    };

    issue(0, 0);
    cpa_commit();
    issue(1, 1);
    cpa_commit();

    int st_next = 2;   // stage index for next issued chunk (kc+2)
    for (int kc = 0; kc < NKC; kc++) {
        if (kc + 2 < NKC) {
            issue(kc + 2, st_next);
            st_next = (st_next == 2) ? 0 : st_next + 1;
            cpa_commit();
            asm volatile("cp.async.wait_group 2;");
        } else if (kc + 1 < NKC) {
            asm volatile("cp.async.wait_group 1;");
        } else {
            asm volatile("cp.async.wait_group 0;");
        }
        __syncthreads();

        const __half* S = gs + (kc % 3) * GS_STAGE;
        const __half* sAh = S;
        const __half* sS1 = S + GS_T;
        const __half* sBh = S + 2 * GS_T;

        #pragma unroll
        for (int kk = 0; kk < 2; kk++) {
            uint32_t ahi[4], alo[4];
            const int arow = 16 * w + (blk & 1) * 8 + lrow;
            const int acol = kk * 16 + (blk >> 1) * 8;
            ldsm_x4(smem_u32(sAh + arow * GSTR + acol), ahi[0], ahi[1], ahi[2], ahi[3]);
            if (useAlo)
                ldsm_x4(smem_u32(sS1 + arow * GSTR + acol), alo[0], alo[1], alo[2], alo[3]);

            #pragma unroll
            for (int np = 0; np < 8; np++) {
                const int brow = np * 16 + (blk >> 1) * 8 + lrow;
                const int bcol = kk * 16 + (blk & 1) * 8;
                uint32_t bh0, bh1, bh2, bh3;
                ldsm_x4(smem_u32(sBh + brow * GSTR + bcol), bh0, bh1, bh2, bh3);
                mma4(acc[2 * np],     ahi, bh0, bh1);
                mma4(acc[2 * np + 1], ahi, bh2, bh3);
                if (useAlo) {
                    mma4(acc[2 * np],     alo, bh0, bh1);
                    mma4(acc[2 * np + 1], alo, bh2, bh3);
                }
                if (useBlo) {
                    uint32_t bl0, bl1, bl2, bl3;
                    ldsm_x4(smem_u32(sS1 + brow * GSTR + bcol), bl0, bl1, bl2, bl3);
                    mma4(acc[2 * np],     ahi, bl0, bl1);
                    mma4(acc[2 * np + 1], ahi, bl2, bl3);
                }
            }
        }
        __syncthreads();
    }

    const float scale = (mode == 2) ? QSCALE : 1.0f;
    const int rloc = 16 * w + (lane >> 2);
    #pragma unroll
    for (int nt = 0; nt < 16; nt++) {
        const int n = col0 + nt * 8 + (lane & 3) * 2;
        const float bx = bias[n], by = bias[n + 1];
        const int m0 = row0 + rloc;
        float o00 = (acc[nt][0] + bx) * scale;
        float o01 = (acc[nt][1] + by) * scale;
        float o10 = (acc[nt][2] + bx) * scale;
        float o11 = (acc[nt][3] + by) * scale;
        if (mode == 0) {
            *(float2*)(outf + (size_t)m0 * D_MODEL + n) = make_float2(o00, o01);
            *(float2*)(outf + (size_t)(m0 + 8) * D_MODEL + n) = make_float2(o10, o11);
        } else {
            const int h = n >> 6, d = n & 63;
            const int b0m = m0 >> 12, s0 = m0 & (SEQ - 1);
            const int b1m = (m0 + 8) >> 12, s1 = (m0 + 8) & (SEQ - 1);
            uint32_t h0u = pk(__floats2half2_rn(o00, o01));
            uint32_t h1u = pk(__floats2half2_rn(o10, o11));
            if (mode == 3) {
                size_t p0 = ((size_t)(b0m * NUM_HEADS + h) * DKH + d) * SEQ + s0;
                size_t p1 = ((size_t)(b1m * NUM_HEADS + h) * DKH + d) * SEQ + s1;
                __half2 H0 = *(__half2*)&h0u, H1 = *(__half2*)&h1u;
                outh[p0] = __low2half(H0);  outh[p0 + SEQ] = __high2half(H0);
                outh[p1] = __low2half(H1);  outh[p1 + SEQ] = __high2half(H1);
            } else {
                size_t p0 = ((size_t)(b0m * NUM_HEADS + h) * SEQ + s0) * DKH + d;
                size_t p1 = ((size_t)(b1m * NUM_HEADS + h) * SEQ + s1) * DKH + d;
                *(uint32_t*)(outh + p0) = h0u;
                *(uint32_t*)(outh + p1) = h1u;
            }
        }
    }
}

__global__ __launch_bounds__(256, 2) void gemm_qkv(
    const float* __restrict__ bq, const float* __restrict__ bk,
    const float* __restrict__ bv)
{
    extern __shared__ __align__(16) __half gs[];
    const int row0 = blockIdx.y * GBM;
    const int col0 = blockIdx.x * GBN;
    if (blockIdx.z == 0)
        gemm_body(gs, row0, col0, g_xqh, g_xql, g_wqh, nullptr, bq, nullptr, g_qh, 2);
    else if (blockIdx.z == 1)
        gemm_body(gs, row0, col0, g_xkh, g_xkl, g_wkh, nullptr, bk, nullptr, g_kh, 1);
    else
        gemm_body(gs, row0, col0, g_xvh, g_xvl, g_wvh, nullptr, bv, nullptr, g_vth, 3);
}

__global__ __launch_bounds__(256, 2) void gemm_out(
    const float* __restrict__ bo, float* __restrict__ outf)
{
    extern __shared__ __align__(16) __half gs[];
    gemm_body(gs, blockIdx.y * GBM, blockIdx.x * GBN,
              g_ath, nullptr, g_woh, g_wol, bo, outf, nullptr, 0);
}

// =========================================================================
// Flash attention (R13 best-measured config, untouched): 128 thr / 4 warps,
// 32 q-rows/warp, 1-pass QK / 1-pass PV, safe-max folded into MMA init,
// KV stage 128 as 4x 32-kv chunks, 2-stage cp.async, 2 CTAs/SM.
// =========================================================================
#define QT 128
#define KVS 128
#define KSTR 72
#define VSTR2 136
#define KTILE2 (KVS * KSTR)
#define VTILE2 (DKH * VSTR2)
#define STG2 (KTILE2 + VTILE2)
#define ATT_SMEM (2 * STG2 * 2)       // 71680 B
#define NT2 (SEQ / KVS)               // 32

__global__ __launch_bounds__(128, 2) void attn_sm(
    const __half* __restrict__ Qh_,
    const __half* __restrict__ Kh_, const __half* __restrict__ VTh_,
    const int* __restrict__ maxk2,
    __half* __restrict__ Oh_)
{
    extern __shared__ __align__(16) __half sStage[];

    const int tid = threadIdx.x;
    const int w = tid >> 5;
    const int lane = tid & 31;
    const int q0 = blockIdx.x * QT;
    const int bh = blockIdx.y;
    const int blk = lane >> 3;
    const int lrow = lane & 7;

    const __half* Qgh = Qh_ + (size_t)bh * SEQ * DKH;
    const __half* Kgh = Kh_ + (size_t)bh * SEQ * DKH;
    const __half* Vgh = VTh_ + (size_t)bh * DKH * SEQ;

    auto issue_kv = [&](int t, int st) {
        const int kt = t * KVS;
        __half* S = sStage + st * STG2;
        #pragma unroll
        for (int i = 0; i < 16; i++) {
            const int ci = tid + i * 128;
            if (ci < 1024) {
                const int r = ci >> 3, c8 = ci & 7;
                cpa16(smem_u32(S + r * KSTR + c8 * 8),
                      Kgh + (size_t)(kt + r) * DKH + c8 * 8);
            } else {
                const int idx = ci - 1024;
                const int r = idx >> 4, c16 = idx & 15;
                cpa16(smem_u32(S + KTILE2 + r * VSTR2 + c16 * 8),
                      Vgh + (size_t)r * SEQ + kt + c16 * 8);
            }
        }
    };

    issue_kv(0, 0);
    cpa_commit();
    issue_kv(1, 1);
    cpa_commit();

    uint32_t qh0[4][4], qh1[4][4];
    const int qr = q0 + 32 * w + (lane >> 2);
    #pragma unroll
    for (int ks = 0; ks < 4; ks++) {
        const int c0 = ks * 16 + (lane & 3) * 2;
        qh0[ks][0] = *(const uint32_t*)(Qgh + (size_t)qr * DKH + c0);
        qh0[ks][1] = *(const uint32_t*)(Qgh + (size_t)(qr + 8) * DKH + c0);
        qh0[ks][2] = *(const uint32_t*)(Qgh + (size_t)qr * DKH + c0 + 8);
        qh0[ks][3] = *(const uint32_t*)(Qgh + (size_t)(qr + 8) * DKH + c0 + 8);
        qh1[ks][0] = *(const uint32_t*)(Qgh + (size_t)(qr + 16) * DKH + c0);
        qh1[ks][1] = *(const uint32_t*)(Qgh + (size_t)(qr + 24) * DKH + c0);
        qh1[ks][2] = *(const uint32_t*)(Qgh + (size_t)(qr + 16) * DKH + c0 + 8);
        qh1[ks][3] = *(const uint32_t*)(Qgh + (size_t)(qr + 24) * DKH + c0 + 8);
    }

    float nq0 = 0.f, nq1 = 0.f, nq2 = 0.f, nq3 = 0.f;
    #pragma unroll
    for (int ks = 0; ks < 4; ks++) {
        nq0 += h2sq(qh0[ks][0]) + h2sq(qh0[ks][2]);
        nq1 += h2sq(qh0[ks][1]) + h2sq(qh0[ks][3]);
        nq2 += h2sq(qh1[ks][0]) + h2sq(qh1[ks][2]);
        nq3 += h2sq(qh1[ks][1]) + h2sq(qh1[ks][3]);
    }
    nq0 += __shfl_xor_sync(0xffffffffu, nq0, 1);
    nq0 += __shfl_xor_sync(0xffffffffu, nq0, 2);
    nq1 += __shfl_xor_sync(0xffffffffu, nq1, 1);
    nq1 += __shfl_xor_sync(0xffffffffu, nq1, 2);
    nq2 += __shfl_xor_sync(0xffffffffu, nq2, 1);
    nq2 += __shfl_xor_sync(0xffffffffu, nq2, 2);
    nq3 += __shfl_xor_sync(0xffffffffu, nq3, 1);
    nq3 += __shfl_xor_sync(0xffffffffu, nq3, 2);
    const float mk = sqrtf(__int_as_float(maxk2[bh]));
    const float M0 = sqrtf(nq0) * mk - SHIFT_LOG2;
    const float M1 = sqrtf(nq1) * mk - SHIFT_LOG2;
    const float M2 = sqrtf(nq2) * mk - SHIFT_LOG2;
    const float M3 = sqrtf(nq3) * mk - SHIFT_LOG2;

    float o0[8][4] = {}, o1[8][4] = {};
    float ls0 = 0.f, ls1 = 0.f, ls2 = 0.f, ls3 = 0.f;

    for (int t = 0; t < NT2; t++) {
        if (t + 1 < NT2) {
            issue_kv(t + 1, (t + 1) & 1);
            cpa_commit();
            asm volatile("cp.async.wait_group 1;");
        } else {
            asm volatile("cp.async.wait_group 0;");
        }
        __syncthreads();

        const __half* S = sStage + (t & 1) * STG2;
        const __half* sKh = S;
        const __half* sVh = S + KTILE2;

        #pragma unroll
        for (int c = 0; c < 4; c++) {
            float s0[4][4], s1[4][4];
            #pragma unroll
            for (int nt = 0; nt < 4; nt++) {
                s0[nt][0] = -M0; s0[nt][1] = -M0; s0[nt][2] = -M1; s0[nt][3] = -M1;
                s1[nt][0] = -M2; s1[nt][1] = -M2; s1[nt][2] = -M3; s1[nt][3] = -M3;
            }
            #pragma unroll
            for (int ks = 0; ks < 4; ks++) {
                #pragma unroll
                for (int np = 0; np < 2; np++) {
                    const int brow = c * 32 + np * 16 + (blk >> 1) * 8 + lrow;
                    const int bcol = ks * 16 + (blk & 1) * 8;
                    uint32_t bh0, bh1, bh2, bh3;
                    ldsm_x4(smem_u32(sKh + brow * KSTR + bcol), bh0, bh1, bh2, bh3);
                    mma4(s0[2 * np],     qh0[ks], bh0, bh1);
                    mma4(s0[2 * np + 1], qh0[ks], bh2, bh3);
                    mma4(s1[2 * np],     qh1[ks], bh0, bh1);
                    mma4(s1[2 * np + 1], qh1[ks], bh2, bh3);
                }
            }

            uint32_t p0[2][4], p1[2][4];
            #pragma unroll
            for (int kk = 0; kk < 2; kk++) {
                float a00 = ex2(s0[2 * kk][0]),     a01 = ex2(s0[2 * kk][1]);
                float a02 = ex2(s0[2 * kk][2]),     a03 = ex2(s0[2 * kk][3]);
                float a10 = ex2(s0[2 * kk + 1][0]), a11 = ex2(s0[2 * kk + 1][1]);
                float a12 = ex2(s0[2 * kk + 1][2]), a13 = ex2(s0[2 * kk + 1][3]);
                ls0 += a00 + a01 + a10 + a11;
                ls1 += a02 + a03 + a12 + a13;
                p0[kk][0] = pk(__floats2half2_rn(a00, a01));
                p0[kk][1] = pk(__floats2half2_rn(a02, a03));
                p0[kk][2] = pk(__floats2half2_rn(a10, a11));
                p0[kk][3] = pk(__floats2half2_rn(a12, a13));

                float b00 = ex2(s1[2 * kk][0]),     b01 = ex2(s1[2 * kk][1]);
                float b02 = ex2(s1[2 * kk][2]),     b03 = ex2(s1[2 * kk][3]);
                float b10 = ex2(s1[2 * kk + 1][0]), b11 = ex2(s1[2 * kk + 1][1]);
                float b12 = ex2(s1[2 * kk + 1][2]), b13 = ex2(s1[2 * kk + 1][3]);
                ls2 += b00 + b01 + b10 + b11;
                ls3 += b02 + b03 + b12 + b13;
                p1[kk][0] = pk(__floats2half2_rn(b00, b01));
                p1[kk][1] = pk(__floats2half2_rn(b02, b03));
                p1[kk][2] = pk(__floats2half2_rn(b10, b11));
                p1[kk][3] = pk(__floats2half2_rn(b12, b13));
            }

            #pragma unroll
            for (int npd = 0; npd < 4; npd++) {
                #pragma unroll
                for (int kk = 0; kk < 2; kk++) {
                    const int vrow = npd * 16 + (blk >> 1) * 8 + lrow;
                    const int vcol = c * 32 + kk * 16 + (blk & 1) * 8;
                    uint32_t vh0, vh1, vh2, vh3;
                    ldsm_x4(smem_u32(sVh + vrow * VSTR2 + vcol), vh0, vh1, vh2, vh3);
                    mma4(o0[2 * npd],     p0[kk], vh0, vh1);
                    mma4(o0[2 * npd + 1], p0[kk], vh2, vh3);
                    mma4(o1[2 * npd],     p1[kk], vh0, vh1);
                    mma4(o1[2 * npd + 1], p1[kk], vh2, vh3);
                }
            }
        }
        __syncthreads();
    }

    ls0 += __shfl_xor_sync(0xffffffffu, ls0, 1);
    ls0 += __shfl_xor_sync(0xffffffffu, ls0, 2);
    ls1 += __shfl_xor_sync(0xffffffffu, ls1, 1);
    ls1 += __shfl_xor_sync(0xffffffffu, ls1, 2);
    ls2 += __shfl_xor_sync(0xffffffffu, ls2, 1);
    ls2 += __shfl_xor_sync(0xffffffffu, ls2, 2);
    ls3 += __shfl_xor_sync(0xffffffffu, ls3, 1);
    ls3 += __shfl_xor_sync(0xffffffffu, ls3, 2);
    const float i0 = 1.f / ls0, i1 = 1.f / ls1, i2 = 1.f / ls2, i3 = 1.f / ls3;

    const int b = bh / NUM_HEADS, h = bh % NUM_HEADS;
    const int r0 = 32 * w + (lane >> 2);
    #pragma unroll
    for (int nt = 0; nt < 8; nt++) {
        const int d = h * DKH + nt * 8 + (lane & 3) * 2;
        size_t pA = (size_t)(b * SEQ + q0 + r0) * D_MODEL + d;
        size_t pB = (size_t)(b * SEQ + q0 + r0 + 8) * D_MODEL + d;
        size_t pC = (size_t)(b * SEQ + q0 + r0 + 16) * D_MODEL + d;
        size_t pD = (size_t)(b * SEQ + q0 + r0 + 24) * D_MODEL + d;
        *(uint32_t*)(Oh_ + pA) = pk(__floats2half2_rn(o0[nt][0] * i0, o0[nt][1] * i0));
        *(uint32_t*)(Oh_ + pB) = pk(__floats2half2_rn(o0[nt][2] * i1, o0[nt][3] * i1));
        *(uint32_t*)(Oh_ + pC) = pk(__floats2half2_rn(o1[nt][0] * i2, o1[nt][1] * i2));
        *(uint32_t*)(Oh_ + pD) = pk(__floats2half2_rn(o1[nt][2] * i3, o1[nt][3] * i3));
    }
}

// =========================================================================
// Launch
// =========================================================================
extern "C" void kernel_launch(void* const* d_in, const int* in_sizes, int n_in,
                              void* d_out, int out_size)
{
    const float* query = (const float*)d_in[0];
    const float* key   = (const float*)d_in[1];
    const float* value = (const float*)d_in[2];
    const float* Wq = (const float*)d_in[3];
    const float* bq = (const float*)d_in[4];
    const float* Wk = (const float*)d_in[5];
    const float* bk = (const float*)d_in[6];
    const float* Wv = (const float*)d_in[7];
    const float* bv = (const float*)d_in[8];
    const float* Wo = (const float*)d_in[9];
    const float* bo = (const float*)d_in[10];
    float* out = (float*)d_out;

    __half *qh, *kh, *vth, *ath;
    int* maxk2;
    cudaGetSymbolAddress((void**)&qh,  g_qh);
    cudaGetSymbolAddress((void**)&kh,  g_kh);
    cudaGetSymbolAddress((void**)&vth, g_vth);
    cudaGetSymbolAddress((void**)&ath, g_ath);
    cudaGetSymbolAddress((void**)&maxk2, g_maxk2);

    cudaFuncSetAttribute(attn_sm, cudaFuncAttributeMaxDynamicSharedMemorySize, ATT_SMEM);
    cudaFuncSetAttribute(gemm_qkv, cudaFuncAttributeMaxDynamicSharedMemorySize, GEM_SMEM);
    cudaFuncSetAttribute(gemm_out, cudaFuncAttributeMaxDynamicSharedMemorySize, GEM_SMEM);

    // single fused converter launch
    dim3 cvt_grid(592, 7);
    cvt_all<<<cvt_grid, 256>>>(query, key, value, Wq, Wk, Wv, Wo);

    // fused Q/K/V projections (2-pass, 128x128 tiles, 3-stage pipeline)
    dim3 qkvgrid(D_MODEL / GBN, MROWS / GBM, 3);   // (6, 64, 3)
    gemm_qkv<<<qkvgrid, 256, GEM_SMEM>>>(bq, bk, bv);

    // kmax
    dim3 kgrid(NBH, 8);
    kmax_kernel<<<kgrid, 256>>>(kh, maxk2);

    // attention (R13 config: grid 768, 4 warps, 32 q-rows/warp, 2 CTAs/SM)
    dim3 agrid(SEQ / QT, NBH);   // (32, 24)
    attn_sm<<<agrid, 128, ATT_SMEM>>>(qh, kh, vth, maxk2, ath);

    // output projection (2-pass B-corrected, 128x128 tiles, 3-stage pipeline)
    dim3 ogrid(D_MODEL / GBN, MROWS / GBM);        // (6, 64)
    gemm_out<<<ogrid, 256, GEM_SMEM>>>(bo, out);
}

// round 17
// speedup vs baseline: 1.0703x; 1.0703x over previous
#include <cuda_runtime.h>
#include <cuda_fp16.h>
#include <math.h>
#include <stdint.h>

#define D_MODEL 768
#define NUM_HEADS 12
#define DKH 64
#define BATCH 2
#define SEQ 4096
#define MROWS (BATCH * SEQ)   // 8192
#define NBH (BATCH * NUM_HEADS)

#define QSCALE 0.18033688011112042f      // log2(e)/8
#define SHIFT_LOG2 5.770780163555855f    // 4 nats in log2

// ---------------- scratch (device globals; no allocation) ----------------
#define QKV_ELEMS ((size_t)NBH * SEQ * DKH)
#define XN ((size_t)MROWS * D_MODEL)
#define WN ((size_t)D_MODEL * D_MODEL)
__device__ __half g_qh[QKV_ELEMS];       // [bh][s][d], prescaled log2e/8, hi only
__device__ __half g_kh[QKV_ELEMS];       // hi only
__device__ __half g_vth[QKV_ELEMS];      // [bh][d][s], hi only
__device__ __half g_xqh[XN], g_xql[XN];
__device__ __half g_xkh[XN], g_xkl[XN];
__device__ __half g_xvh[XN], g_xvl[XN];
__device__ __half g_wqh[WN];
__device__ __half g_wkh[WN];
__device__ __half g_wvh[WN];
__device__ __half g_woh[WN], g_wol[WN];
__device__ __half g_ath[XN];             // attention out, hi only
__device__ int    g_maxk2[NBH];          // max ||k||^2 as float bits (atomicMax)

// ---------------- helpers ----------------
__device__ __forceinline__ uint32_t smem_u32(const void* p) {
    return (uint32_t)__cvta_generic_to_shared(p);
}
__device__ __forceinline__ uint32_t pk(__half2 h) {
    union { __half2 h; uint32_t u; } x; x.h = h; return x.u;
}
__device__ __forceinline__ void ldsm_x4(uint32_t a, uint32_t& r0, uint32_t& r1,
                                        uint32_t& r2, uint32_t& r3) {
    asm volatile("ldmatrix.sync.aligned.m8n8.x4.shared.b16 {%0,%1,%2,%3}, [%4];"
                 : "=r"(r0), "=r"(r1), "=r"(r2), "=r"(r3) : "r"(a));
}
__device__ __forceinline__ void mma4(float* c, const uint32_t* a, uint32_t b0, uint32_t b1) {
    asm volatile(
        "mma.sync.aligned.m16n8k16.row.col.f32.f16.f16.f32 "
        "{%0,%1,%2,%3}, {%4,%5,%6,%7}, {%8,%9}, {%0,%1,%2,%3};"
        : "+f"(c[0]), "+f"(c[1]), "+f"(c[2]), "+f"(c[3])
        : "r"(a[0]), "r"(a[1]), "r"(a[2]), "r"(a[3]), "r"(b0), "r"(b1));
}
__device__ __forceinline__ void split2(float x, float y, uint32_t& hi, uint32_t& lo) {
    __half2 h = __floats2half2_rn(x, y);
    float rx = x - __half2float(__low2half(h));
    float ry = y - __half2float(__high2half(h));
    hi = pk(h);
    lo = pk(__floats2half2_rn(rx, ry));
}
__device__ __forceinline__ void cpa16(uint32_t s, const void* g) {
    asm volatile("cp.async.cg.shared.global [%0], [%1], 16;" :: "r"(s), "l"(g));
}
__device__ __forceinline__ void cpa_commit() {
    asm volatile("cp.async.commit_group;");
}
__device__ __forceinline__ float ex2(float x) {
    float y;
    asm("ex2.approx.f32 %0, %1;" : "=f"(y) : "f"(x));
    return y;
}
__device__ __forceinline__ float h2sq(uint32_t u) {
    float2 f = __half22float2(*(__half2*)&u);
    return f.x * f.x + f.y * f.y;
}

// =========================================================================
// Fused converter: y = 0..2 activations hi+lo; 3..5 weights hi; 6 Wo hi+lo.
// =========================================================================
__global__ __launch_bounds__(256) void cvt_all(
    const float* __restrict__ q, const float* __restrict__ k,
    const float* __restrict__ v, const float* __restrict__ wq,
    const float* __restrict__ wk, const float* __restrict__ wv,
    const float* __restrict__ wo)
{
    const int y = blockIdx.y;
    const float* src;
    __half *hi, *lo;
    int n4;
    switch (y) {
        case 0: src = q;  hi = g_xqh; lo = g_xql;   n4 = XN / 4; break;
        case 1: src = k;  hi = g_xkh; lo = g_xkl;   n4 = XN / 4; break;
        case 2: src = v;  hi = g_xvh; lo = g_xvl;   n4 = XN / 4; break;
        case 3: src = wq; hi = g_wqh; lo = nullptr; n4 = WN / 4; break;
        case 4: src = wk; hi = g_wkh; lo = nullptr; n4 = WN / 4; break;
        case 5: src = wv; hi = g_wvh; lo = nullptr; n4 = WN / 4; break;
        default: src = wo; hi = g_woh; lo = g_wol;  n4 = WN / 4; break;
    }
    uint32_t* hio = (uint32_t*)hi;
    uint32_t* loo = (uint32_t*)lo;
    for (int i = blockIdx.x * 256 + threadIdx.x; i < n4; i += gridDim.x * 256) {
        float4 f = ((const float4*)src)[i];
        uint32_t h0, l0, h1, l1;
        split2(f.x, f.y, h0, l0);
        split2(f.z, f.w, h1, l1);
        hio[2 * i] = h0; hio[2 * i + 1] = h1;
        if (lo) { loo[2 * i] = l0; loo[2 * i + 1] = l1; }
    }
}

// =========================================================================
// kmax: grid (NBH, 8), atomicMax on float bits of ||k||^2 (all >= 0).
// =========================================================================
__global__ __launch_bounds__(256) void kmax_kernel(const __half* __restrict__ kh,
                                                   int* __restrict__ maxk2)
{
    __shared__ float red[256];
    const int bh = blockIdx.x;
    const int part = blockIdx.y;
    const int rows = SEQ / 8;
    const __half* base = kh + (size_t)bh * SEQ * DKH + (size_t)part * rows * DKH;
    float mx = 0.f;
    for (int r = threadIdx.x; r < rows; r += 256) {
        const uint4* p = (const uint4*)(base + (size_t)r * DKH);
        float s = 0.f;
        #pragma unroll
        for (int i = 0; i < 8; i++) {
            uint4 u = p[i];
            s += h2sq(u.x) + h2sq(u.y) + h2sq(u.z) + h2sq(u.w);
        }
        mx = fmaxf(mx, s);
    }
    red[threadIdx.x] = mx;
    __syncthreads();
    for (int st = 128; st > 0; st >>= 1) {
        if (threadIdx.x < st) red[threadIdx.x] = fmaxf(red[threadIdx.x], red[threadIdx.x + st]);
        __syncthreads();
    }
    if (threadIdx.x == 0) atomicMax(&maxk2[bh], __float_as_int(red[0]));
}

// =========================================================================
// GEMM body, tile 128x128, K-chunk 32, 3-stage cp.async, ONE sync per chunk
// (stage overwritten at iter kc was last read at kc-1, fenced by top sync).
// SMEM slots per stage: [0]=A hi, [1]=A lo OR W lo, [2]=W hi.
// =========================================================================
#define GBM 128
#define GBN 128
#define GKC 32
#define GSTR 40
#define NKC (D_MODEL / GKC)      // 24
#define GS_T (128 * GSTR)
#define GS_STAGE (3 * GS_T)
#define GEM_SMEM (3 * GS_STAGE * 2)  // 92160 bytes

__device__ __forceinline__ void gemm_body(
    __half* gs, int row0, int col0,
    const __half* __restrict__ Ah, const __half* __restrict__ Al,
    const __half* __restrict__ Wh, const __half* __restrict__ Wl,
    const float* __restrict__ bias, float* __restrict__ outf,
    __half* __restrict__ outh, int mode)
{
    const int tid = threadIdx.x;
    const int w = tid >> 5;
    const int lane = tid & 31;
    const int blk = lane >> 3;
    const int lrow = lane & 7;
    const bool useAlo = (Al != nullptr);
    const bool useBlo = (Wl != nullptr);

    float acc[16][4] = {};

    auto issue = [&](int kc, int st) {
        const int k0 = kc * GKC;
        __half* S = gs + st * GS_STAGE;
        #pragma unroll
        for (int i = 0; i < 6; i++) {
            const int ci = tid + i * 256;
            const int slot = ci >> 9;
            const int idx = ci & 511;
            const int r = idx >> 2, c4 = idx & 3;
            const __half* src;
            if (slot == 0) {
                src = Ah + (size_t)(row0 + r) * D_MODEL + k0 + c4 * 8;
            } else if (slot == 1) {
                if (useAlo)      src = Al + (size_t)(row0 + r) * D_MODEL + k0 + c4 * 8;
                else if (useBlo) src = Wl + (size_t)(col0 + r) * D_MODEL + k0 + c4 * 8;
                else continue;
            } else {
                src = Wh + (size_t)(col0 + r) * D_MODEL + k0 + c4 * 8;
            }
            cpa16(smem_u32(S + slot * GS_T + r * GSTR + c4 * 8), src);
        }
    };

    issue(0, 0);
    cpa_commit();
    issue(1, 1);
    cpa_commit();

    for (int kc = 0; kc < NKC; kc++) {
        if (kc + 1 < NKC) {
            asm volatile("cp.async.wait_group 1;");
        } else {
            asm volatile("cp.async.wait_group 0;");
        }
        __syncthreads();

        const __half* S = gs + (kc % 3) * GS_STAGE;
        const __half* sAh = S;
        const __half* sS1 = S + GS_T;
        const __half* sBh = S + 2 * GS_T;

        #pragma unroll
        for (int kk = 0; kk < 2; kk++) {
            uint32_t ahi[4], alo[4];
            const int arow = 16 * w + (blk & 1) * 8 + lrow;
            const int acol = kk * 16 + (blk >> 1) * 8;
            ldsm_x4(smem_u32(sAh + arow * GSTR + acol), ahi[0], ahi[1], ahi[2], ahi[3]);
            if (useAlo)
                ldsm_x4(smem_u32(sS1 + arow * GSTR + acol), alo[0], alo[1], alo[2], alo[3]);

            #pragma unroll
            for (int np = 0; np < 8; np++) {
                const int brow = np * 16 + (blk >> 1) * 8 + lrow;
                const int bcol = kk * 16 + (blk & 1) * 8;
                uint32_t bh0, bh1, bh2, bh3;
                ldsm_x4(smem_u32(sBh + brow * GSTR + bcol), bh0, bh1, bh2, bh3);
                mma4(acc[2 * np],     ahi, bh0, bh1);
                mma4(acc[2 * np + 1], ahi, bh2, bh3);
                if (useAlo) {
                    mma4(acc[2 * np],     alo, bh0, bh1);
                    mma4(acc[2 * np + 1], alo, bh2, bh3);
                }
                if (useBlo) {
                    uint32_t bl0, bl1, bl2, bl3;
                    ldsm_x4(smem_u32(sS1 + brow * GSTR + bcol), bl0, bl1, bl2, bl3);
                    mma4(acc[2 * np],     ahi, bl0, bl1);
                    mma4(acc[2 * np + 1], ahi, bl2, bl3);
                }
            }
        }

        // issue next+1 chunk into the stage read at kc-1 (fenced by top sync)
        if (kc + 2 < NKC) {
            issue(kc + 2, (kc + 2) % 3);
            cpa_commit();
        }
    }

    const float scale = (mode == 2) ? QSCALE : 1.0f;
    const int rloc = 16 * w + (lane >> 2);
    #pragma unroll
    for (int nt = 0; nt < 16; nt++) {
        const int n = col0 + nt * 8 + (lane & 3) * 2;
        const float bx = bias[n], by = bias[n + 1];
        const int m0 = row0 + rloc;
        float o00 = (acc[nt][0] + bx) * scale;
        float o01 = (acc[nt][1] + by) * scale;
        float o10 = (acc[nt][2] + bx) * scale;
        float o11 = (acc[nt][3] + by) * scale;
        if (mode == 0) {
            *(float2*)(outf + (size_t)m0 * D_MODEL + n) = make_float2(o00, o01);
            *(float2*)(outf + (size_t)(m0 + 8) * D_MODEL + n) = make_float2(o10, o11);
        } else {
            const int h = n >> 6, d = n & 63;
            const int b0m = m0 >> 12, s0 = m0 & (SEQ - 1);
            const int b1m = (m0 + 8) >> 12, s1 = (m0 + 8) & (SEQ - 1);
            uint32_t h0u = pk(__floats2half2_rn(o00, o01));
            uint32_t h1u = pk(__floats2half2_rn(o10, o11));
            if (mode == 3) {
                size_t p0 = ((size_t)(b0m * NUM_HEADS + h) * DKH + d) * SEQ + s0;
                size_t p1 = ((size_t)(b1m * NUM_HEADS + h) * DKH + d) * SEQ + s1;
                __half2 H0 = *(__half2*)&h0u, H1 = *(__half2*)&h1u;
                outh[p0] = __low2half(H0);  outh[p0 + SEQ] = __high2half(H0);
                outh[p1] = __low2half(H1);  outh[p1 + SEQ] = __high2half(H1);
            } else {
                size_t p0 = ((size_t)(b0m * NUM_HEADS + h) * SEQ + s0) * DKH + d;
                size_t p1 = ((size_t)(b1m * NUM_HEADS + h) * SEQ + s1) * DKH + d;
                *(uint32_t*)(outh + p0) = h0u;
                *(uint32_t*)(outh + p1) = h1u;
            }
        }
    }
}

__global__ __launch_bounds__(256, 2) void gemm_qkv(
    const float* __restrict__ bq, const float* __restrict__ bk,
    const float* __restrict__ bv)
{
    extern __shared__ __align__(16) __half gs[];
    const int row0 = blockIdx.y * GBM;
    const int col0 = blockIdx.x * GBN;
    if (blockIdx.z == 0)
        gemm_body(gs, row0, col0, g_xqh, g_xql, g_wqh, nullptr, bq, nullptr, g_qh, 2);
    else if (blockIdx.z == 1)
        gemm_body(gs, row0, col0, g_xkh, g_xkl, g_wkh, nullptr, bk, nullptr, g_kh, 1);
    else
        gemm_body(gs, row0, col0, g_xvh, g_xvl, g_wvh, nullptr, bv, nullptr, g_vth, 3);
}

__global__ __launch_bounds__(256, 2) void gemm_out(
    const float* __restrict__ bo, float* __restrict__ outf)
{
    extern __shared__ __align__(16) __half gs[];
    gemm_body(gs, blockIdx.y * GBM, blockIdx.x * GBN,
              g_ath, nullptr, g_woh, g_wol, bo, outf, nullptr, 0);
}

// =========================================================================
// Flash attention: R13 compute config, now with 3-stage KV ring and ONE
// __syncthreads per KV tile. 128 thr / 4 warps, 32 q-rows/warp, 1-pass QK /
// 1-pass PV, safe-max folded into MMA init, 4x 32-kv chunks, 2 CTAs/SM.
// SMEM: 3 x (K 128x72 + V^T 64x136) halves = 107520 B.
// =========================================================================
#define QT 128
#define KVS 128
#define KSTR 72
#define VSTR2 136
#define KTILE2 (KVS * KSTR)
#define VTILE2 (DKH * VSTR2)
#define STG2 (KTILE2 + VTILE2)
#define ATT_SMEM (3 * STG2 * 2)       // 107520 B
#define NT2 (SEQ / KVS)               // 32

__global__ __launch_bounds__(128, 2) void attn_sm(
    const __half* __restrict__ Qh_,
    const __half* __restrict__ Kh_, const __half* __restrict__ VTh_,
    const int* __restrict__ maxk2,
    __half* __restrict__ Oh_)
{
    extern __shared__ __align__(16) __half sStage[];

    const int tid = threadIdx.x;
    const int w = tid >> 5;
    const int lane = tid & 31;
    const int q0 = blockIdx.x * QT;
    const int bh = blockIdx.y;
    const int blk = lane >> 3;
    const int lrow = lane & 7;

    const __half* Qgh = Qh_ + (size_t)bh * SEQ * DKH;
    const __half* Kgh = Kh_ + (size_t)bh * SEQ * DKH;
    const __half* Vgh = VTh_ + (size_t)bh * DKH * SEQ;

    auto issue_kv = [&](int t, int st) {
        const int kt = t * KVS;
        __half* S = sStage + st * STG2;
        #pragma unroll
        for (int i = 0; i < 16; i++) {
            const int ci = tid + i * 128;
            if (ci < 1024) {
                const int r = ci >> 3, c8 = ci & 7;
                cpa16(smem_u32(S + r * KSTR + c8 * 8),
                      Kgh + (size_t)(kt + r) * DKH + c8 * 8);
            } else {
                const int idx = ci - 1024;
                const int r = idx >> 4, c16 = idx & 15;
                cpa16(smem_u32(S + KTILE2 + r * VSTR2 + c16 * 8),
                      Vgh + (size_t)r * SEQ + kt + c16 * 8);
            }
        }
    };

    issue_kv(0, 0);
    cpa_commit();
    issue_kv(1, 1);
    cpa_commit();

    uint32_t qh0[4][4], qh1[4][4];
    const int qr = q0 + 32 * w + (lane >> 2);
    #pragma unroll
    for (int ks = 0; ks < 4; ks++) {
        const int c0 = ks * 16 + (lane & 3) * 2;
        qh0[ks][0] = *(const uint32_t*)(Qgh + (size_t)qr * DKH + c0);
        qh0[ks][1] = *(const uint32_t*)(Qgh + (size_t)(qr + 8) * DKH + c0);
        qh0[ks][2] = *(const uint32_t*)(Qgh + (size_t)qr * DKH + c0 + 8);
        qh0[ks][3] = *(const uint32_t*)(Qgh + (size_t)(qr + 8) * DKH + c0 + 8);
        qh1[ks][0] = *(const uint32_t*)(Qgh + (size_t)(qr + 16) * DKH + c0);
        qh1[ks][1] = *(const uint32_t*)(Qgh + (size_t)(qr + 24) * DKH + c0);
        qh1[ks][2] = *(const uint32_t*)(Qgh + (size_t)(qr + 16) * DKH + c0 + 8);
        qh1[ks][3] = *(const uint32_t*)(Qgh + (size_t)(qr + 24) * DKH + c0 + 8);
    }

    float nq0 = 0.f, nq1 = 0.f, nq2 = 0.f, nq3 = 0.f;
    #pragma unroll
    for (int ks = 0; ks < 4; ks++) {
        nq0 += h2sq(qh0[ks][0]) + h2sq(qh0[ks][2]);
        nq1 += h2sq(qh0[ks][1]) + h2sq(qh0[ks][3]);
        nq2 += h2sq(qh1[ks][0]) + h2sq(qh1[ks][2]);
        nq3 += h2sq(qh1[ks][1]) + h2sq(qh1[ks][3]);
    }
    nq0 += __shfl_xor_sync(0xffffffffu, nq0, 1);
    nq0 += __shfl_xor_sync(0xffffffffu, nq0, 2);
    nq1 += __shfl_xor_sync(0xffffffffu, nq1, 1);
    nq1 += __shfl_xor_sync(0xffffffffu, nq1, 2);
    nq2 += __shfl_xor_sync(0xffffffffu, nq2, 1);
    nq2 += __shfl_xor_sync(0xffffffffu, nq2, 2);
    nq3 += __shfl_xor_sync(0xffffffffu, nq3, 1);
    nq3 += __shfl_xor_sync(0xffffffffu, nq3, 2);
    const float mk = sqrtf(__int_as_float(maxk2[bh]));
    const float M0 = sqrtf(nq0) * mk - SHIFT_LOG2;
    const float M1 = sqrtf(nq1) * mk - SHIFT_LOG2;
    const float M2 = sqrtf(nq2) * mk - SHIFT_LOG2;
    const float M3 = sqrtf(nq3) * mk - SHIFT_LOG2;

    float o0[8][4] = {}, o1[8][4] = {};
    float ls0 = 0.f, ls1 = 0.f, ls2 = 0.f, ls3 = 0.f;

    for (int t = 0; t < NT2; t++) {
        if (t + 1 < NT2) {
            asm volatile("cp.async.wait_group 1;");
        } else {
            asm volatile("cp.async.wait_group 0;");
        }
        __syncthreads();

        const __half* S = sStage + (t % 3) * STG2;
        const __half* sKh = S;
        const __half* sVh = S + KTILE2;

        #pragma unroll
        for (int c = 0; c < 4; c++) {
            float s0[4][4], s1[4][4];
            #pragma unroll
            for (int nt = 0; nt < 4; nt++) {
                s0[nt][0] = -M0; s0[nt][1] = -M0; s0[nt][2] = -M1; s0[nt][3] = -M1;
                s1[nt][0] = -M2; s1[nt][1] = -M2; s1[nt][2] = -M3; s1[nt][3] = -M3;
            }
            #pragma unroll
            for (int ks = 0; ks < 4; ks++) {
                #pragma unroll
                for (int np = 0; np < 2; np++) {
                    const int brow = c * 32 + np * 16 + (blk >> 1) * 8 + lrow;
                    const int bcol = ks * 16 + (blk & 1) * 8;
                    uint32_t bh0, bh1, bh2, bh3;
                    ldsm_x4(smem_u32(sKh + brow * KSTR + bcol), bh0, bh1, bh2, bh3);
                    mma4(s0[2 * np],     qh0[ks], bh0, bh1);
                    mma4(s0[2 * np + 1], qh0[ks], bh2, bh3);
                    mma4(s1[2 * np],     qh1[ks], bh0, bh1);
                    mma4(s1[2 * np + 1], qh1[ks], bh2, bh3);
                }
            }

            uint32_t p0[2][4], p1[2][4];
            #pragma unroll
            for (int kk = 0; kk < 2; kk++) {
                float a00 = ex2(s0[2 * kk][0]),     a01 = ex2(s0[2 * kk][1]);
                float a02 = ex2(s0[2 * kk][2]),     a03 = ex2(s0[2 * kk][3]);
                float a10 = ex2(s0[2 * kk + 1][0]), a11 = ex2(s0[2 * kk + 1][1]);
                float a12 = ex2(s0[2 * kk + 1][2]), a13 = ex2(s0[2 * kk + 1][3]);
                ls0 += a00 + a01 + a10 + a11;
                ls1 += a02 + a03 + a12 + a13;
                p0[kk][0] = pk(__floats2half2_rn(a00, a01));
                p0[kk][1] = pk(__floats2half2_rn(a02, a03));
                p0[kk][2] = pk(__floats2half2_rn(a10, a11));
                p0[kk][3] = pk(__floats2half2_rn(a12, a13));

                float b00 = ex2(s1[2 * kk][0]),     b01 = ex2(s1[2 * kk][1]);
                float b02 = ex2(s1[2 * kk][2]),     b03 = ex2(s1[2 * kk][3]);
                float b10 = ex2(s1[2 * kk + 1][0]), b11 = ex2(s1[2 * kk + 1][1]);
                float b12 = ex2(s1[2 * kk + 1][2]), b13 = ex2(s1[2 * kk + 1][3]);
                ls2 += b00 + b01 + b10 + b11;
                ls3 += b02 + b03 + b12 + b13;
                p1[kk][0] = pk(__floats2half2_rn(b00, b01));
                p1[kk][1] = pk(__floats2half2_rn(b02, b03));
                p1[kk][2] = pk(__floats2half2_rn(b10, b11));
                p1[kk][3] = pk(__floats2half2_rn(b12, b13));
            }

            #pragma unroll
            for (int npd = 0; npd < 4; npd++) {
                #pragma unroll
                for (int kk = 0; kk < 2; kk++) {
                    const int vrow = npd * 16 + (blk >> 1) * 8 + lrow;
                    const int vcol = c * 32 + kk * 16 + (blk & 1) * 8;
                    uint32_t vh0, vh1, vh2, vh3;
                    ldsm_x4(smem_u32(sVh + vrow * VSTR2 + vcol), vh0, vh1, vh2, vh3);
                    mma4(o0[2 * npd],     p0[kk], vh0, vh1);
                    mma4(o0[2 * npd + 1], p0[kk], vh2, vh3);
                    mma4(o1[2 * npd],     p1[kk], vh0, vh1);
                    mma4(o1[2 * npd + 1], p1[kk], vh2, vh3);
                }
            }
        }

        // issue tile t+2 into the stage read at t-1 (fenced by top sync)
        if (t + 2 < NT2) {
            issue_kv(t + 2, (t + 2) % 3);
            cpa_commit();
        }
    }

    ls0 += __shfl_xor_sync(0xffffffffu, ls0, 1);
    ls0 += __shfl_xor_sync(0xffffffffu, ls0, 2);
    ls1 += __shfl_xor_sync(0xffffffffu, ls1, 1);
    ls1 += __shfl_xor_sync(0xffffffffu, ls1, 2);
    ls2 += __shfl_xor_sync(0xffffffffu, ls2, 1);
    ls2 += __shfl_xor_sync(0xffffffffu, ls2, 2);
    ls3 += __shfl_xor_sync(0xffffffffu, ls3, 1);
    ls3 += __shfl_xor_sync(0xffffffffu, ls3, 2);
    const float i0 = 1.f / ls0, i1 = 1.f / ls1, i2 = 1.f / ls2, i3 = 1.f / ls3;

    const int b = bh / NUM_HEADS, h = bh % NUM_HEADS;
    const int r0 = 32 * w + (lane >> 2);
    #pragma unroll
    for (int nt = 0; nt < 8; nt++) {
        const int d = h * DKH + nt * 8 + (lane & 3) * 2;
        size_t pA = (size_t)(b * SEQ + q0 + r0) * D_MODEL + d;
        size_t pB = (size_t)(b * SEQ + q0 + r0 + 8) * D_MODEL + d;
        size_t pC = (size_t)(b * SEQ + q0 + r0 + 16) * D_MODEL + d;
        size_t pD = (size_t)(b * SEQ + q0 + r0 + 24) * D_MODEL + d;
        *(uint32_t*)(Oh_ + pA) = pk(__floats2half2_rn(o0[nt][0] * i0, o0[nt][1] * i0));
        *(uint32_t*)(Oh_ + pB) = pk(__floats2half2_rn(o0[nt][2] * i1, o0[nt][3] * i1));
        *(uint32_t*)(Oh_ + pC) = pk(__floats2half2_rn(o1[nt][0] * i2, o1[nt][1] * i2));
        *(uint32_t*)(Oh_ + pD) = pk(__floats2half2_rn(o1[nt][2] * i3, o1[nt][3] * i3));
    }
}

// =========================================================================
// Launch
// =========================================================================
extern "C" void kernel_launch(void* const* d_in, const int* in_sizes, int n_in,
                              void* d_out, int out_size)
{
    const float* query = (const float*)d_in[0];
    const float* key   = (const float*)d_in[1];
    const float* value = (const float*)d_in[2];
    const float* Wq = (const float*)d_in[3];
    const float* bq = (const float*)d_in[4];
    const float* Wk = (const float*)d_in[5];
    const float* bk = (const float*)d_in[6];
    const float* Wv = (const float*)d_in[7];
    const float* bv = (const float*)d_in[8];
    const float* Wo = (const float*)d_in[9];
    const float* bo = (const float*)d_in[10];
    float* out = (float*)d_out;

    __half *qh, *kh, *vth, *ath;
    int* maxk2;
    cudaGetSymbolAddress((void**)&qh,  g_qh);
    cudaGetSymbolAddress((void**)&kh,  g_kh);
    cudaGetSymbolAddress((void**)&vth, g_vth);
    cudaGetSymbolAddress((void**)&ath, g_ath);
    cudaGetSymbolAddress((void**)&maxk2, g_maxk2);

    cudaFuncSetAttribute(attn_sm, cudaFuncAttributeMaxDynamicSharedMemorySize, ATT_SMEM);
    cudaFuncSetAttribute(gemm_qkv, cudaFuncAttributeMaxDynamicSharedMemorySize, GEM_SMEM);
    cudaFuncSetAttribute(gemm_out, cudaFuncAttributeMaxDynamicSharedMemorySize, GEM_SMEM);

    // single fused converter launch
    dim3 cvt_grid(592, 7);
    cvt_all<<<cvt_grid, 256>>>(query, key, value, Wq, Wk, Wv, Wo);

    // fused Q/K/V projections (2-pass, 128x128 tiles, 3-stage, 1 sync/chunk)
    dim3 qkvgrid(D_MODEL / GBN, MROWS / GBM, 3);   // (6, 64, 3)
    gemm_qkv<<<qkvgrid, 256, GEM_SMEM>>>(bq, bk, bv);

    // kmax
    dim3 kgrid(NBH, 8);
    kmax_kernel<<<kgrid, 256>>>(kh, maxk2);

    // attention (3-stage KV ring, 1 sync/tile)
    dim3 agrid(SEQ / QT, NBH);   // (32, 24)
    attn_sm<<<agrid, 128, ATT_SMEM>>>(qh, kh, vth, maxk2, ath);

    // output projection (2-pass B-corrected)
    dim3 ogrid(D_MODEL / GBN, MROWS / GBM);        // (6, 64)
    gemm_out<<<ogrid, 256, GEM_SMEM>>>(bo, out);
}